// round 3
// baseline (speedup 1.0000x reference)
#include <cuda_runtime.h>

// MultiClassDiceScore: 3x 5-bin histograms over 33.5M voxels, SIMD nibble/PRMT
// formulation, fused finalize (last-block-done). Memory-bound: 268 MB once.
//
// g_hist layout: [0..3]=pred cnt c0..3, [4..7]=mask cnt c0..3,
//                [8..11]=agree cnt c0..3, [12]=total agreements.
// Class-4 bins derived in the fused finalize. The last block re-zeroes
// g_hist/g_done so every graph replay starts from a clean state.

#define DICE_EPS 1e-7f
#define GRID_BLOCKS 740

__device__ unsigned int g_hist[16];   // zero-initialized at module load
__device__ unsigned int g_done;       // block-completion counter

__device__ __forceinline__ unsigned int prmt(unsigned int a, unsigned int b, unsigned int s) {
    unsigned int d;
    asm("prmt.b32 %0, %1, %2, %3;" : "=r"(d) : "r"(a), "r"(b), "r"(s));
    return d;
}

__device__ __forceinline__ unsigned long long addf32x2(unsigned long long a, unsigned long long b) {
    unsigned long long d;
    asm("add.rn.f32x2 %0, %1, %2;" : "=l"(d) : "l"(a), "l"(b));
    return d;
}

// Pack constants: lo half adds 2^23 (label -> bits[0:4)), hi half adds 2^19
// (label -> bits[4:8)), etc. All sums exact in fp32 for labels 0..4.
#define C01 0x490000004B000000ull   // {2^23, 2^19}
#define C23 0x4500000047000000ull   // {2^15, 2^11}

__global__ __launch_bounds__(256, 5)
void dice_main_kernel(const ulonglong2* __restrict__ pred2,
                      const int4* __restrict__ mask4,
                      int nvec, int n_total,
                      float* __restrict__ out) {
    // Byte-lane accumulators: byte k of aX counts elements at lane k of each
    // 4-element group. Max per-thread groups ~45 << 255: no overflow.
    unsigned int aP0 = 0, aP1 = 0, aP2 = 0, aP3 = 0;
    unsigned int aM0 = 0, aM1 = 0, aM2 = 0, aM3 = 0;
    unsigned int aN0 = 0, aN1 = 0, aN2 = 0, aN3 = 0;
    unsigned int aZ  = 0;

    const int stride = gridDim.x * blockDim.x;
    int i = blockIdx.x * blockDim.x + threadIdx.x;

#pragma unroll 4
    for (; i < nvec; i += stride) {
        ulonglong2 p = __ldcs(&pred2[i]);   // 4 float labels
        int4       m = __ldcs(&mask4[i]);   // 4 int labels

        // selP nibbles = [p0,p1,p2,p3] via packed-f32 exponent trick.
        unsigned long long a01 = addf32x2(p.x, C01);
        unsigned long long a23 = addf32x2(p.y, C23);
        unsigned int selP = (unsigned int)a01 | (unsigned int)(a01 >> 32)
                          | (unsigned int)a23 | (unsigned int)(a23 >> 32);
        // selM nibbles = [m0,m1,m2,m3]
        unsigned int selM = (unsigned int)m.x + ((unsigned int)m.y << 4)
                          + ((unsigned int)m.z << 8) + ((unsigned int)m.w << 12);

        // zd byte k = 1 iff p_k == m_k  (nibble-zero detect, one PRMT LUT)
        unsigned int agr = selP ^ selM;           // nibbles in [0,7]
        unsigned int zd  = prmt(0x00000001u, 0u, agr);
        aZ += zd;

        // per-class equality bytes via PRMT LUTs (classes 0..3; 4 derived)
        unsigned int eP0 = prmt(0x00000001u, 0u, selP);
        unsigned int eP1 = prmt(0x00000100u, 0u, selP);
        unsigned int eP2 = prmt(0x00010000u, 0u, selP);
        unsigned int eP3 = prmt(0x01000000u, 0u, selP);
        aP0 += eP0; aP1 += eP1; aP2 += eP2; aP3 += eP3;

        unsigned int eM0 = prmt(0x00000001u, 0u, selM);
        unsigned int eM1 = prmt(0x00000100u, 0u, selM);
        unsigned int eM2 = prmt(0x00010000u, 0u, selM);
        unsigned int eM3 = prmt(0x01000000u, 0u, selM);
        aM0 += eM0; aM1 += eM1; aM2 += eM2; aM3 += eM3;

        aN0 += eP0 & zd; aN1 += eP1 & zd; aN2 += eP2 & zd; aN3 += eP3 & zd;
    }

    // Horizontal byte sums, warp reduce, block reduce, 13 global atomics/block.
    unsigned int v[13];
    v[0]  = (unsigned int)__dp4a((int)aP0, 0x01010101, 0);
    v[1]  = (unsigned int)__dp4a((int)aP1, 0x01010101, 0);
    v[2]  = (unsigned int)__dp4a((int)aP2, 0x01010101, 0);
    v[3]  = (unsigned int)__dp4a((int)aP3, 0x01010101, 0);
    v[4]  = (unsigned int)__dp4a((int)aM0, 0x01010101, 0);
    v[5]  = (unsigned int)__dp4a((int)aM1, 0x01010101, 0);
    v[6]  = (unsigned int)__dp4a((int)aM2, 0x01010101, 0);
    v[7]  = (unsigned int)__dp4a((int)aM3, 0x01010101, 0);
    v[8]  = (unsigned int)__dp4a((int)aN0, 0x01010101, 0);
    v[9]  = (unsigned int)__dp4a((int)aN1, 0x01010101, 0);
    v[10] = (unsigned int)__dp4a((int)aN2, 0x01010101, 0);
    v[11] = (unsigned int)__dp4a((int)aN3, 0x01010101, 0);
    v[12] = (unsigned int)__dp4a((int)aZ,  0x01010101, 0);

    __shared__ unsigned int sh[13];
    __shared__ bool is_last;
    if (threadIdx.x < 13) sh[threadIdx.x] = 0u;
    __syncthreads();

#pragma unroll
    for (int k = 0; k < 13; k++) {
        unsigned int w = __reduce_add_sync(0xFFFFFFFFu, v[k]);
        if ((threadIdx.x & 31) == 0) atomicAdd(&sh[k], w);
    }
    __syncthreads();
    if (threadIdx.x < 13) atomicAdd(&g_hist[threadIdx.x], sh[threadIdx.x]);

    // Last-block-done: the final arriving block computes dice + resets state.
    if (threadIdx.x == 0) {
        __threadfence();
        unsigned int old = atomicAdd(&g_done, 1u);
        is_last = (old == (unsigned int)(gridDim.x - 1));
    }
    __syncthreads();

    if (is_last && threadIdx.x == 0) {
        unsigned int P[5], M[5], Nm[5];
        unsigned int sp = 0, sm = 0, sn = 0;
#pragma unroll
        for (int c = 0; c < 4; c++) {
            P[c]  = g_hist[c];       sp += P[c];
            M[c]  = g_hist[4 + c];   sm += M[c];
            Nm[c] = g_hist[8 + c];   sn += Nm[c];
        }
        unsigned int Z = g_hist[12];
        P[4]  = (unsigned int)n_total - sp;
        M[4]  = (unsigned int)n_total - sm;
        Nm[4] = Z - sn;

        float s = 0.0f;
#pragma unroll
        for (int c = 0; c < 5; c++) {
            float den1 = (float)P[c];
            float den2 = (float)M[c];
            float num  = (float)Nm[c];
            s += 2.0f * ((num + DICE_EPS) / (den1 + den2 + DICE_EPS));
        }
        out[0] = s * 0.2f;

        // reset state for the next (graph-replayed) launch
#pragma unroll
        for (int k = 0; k < 16; k++) g_hist[k] = 0u;
        __threadfence();
        g_done = 0u;
    }
}

extern "C" void kernel_launch(void* const* d_in, const int* in_sizes, int n_in,
                              void* d_out, int out_size) {
    const float* pred = (const float*)d_in[0];  // [128,1,512,512] f32, values 0..4
    const int*   mask = (const int*)d_in[1];    // [1,128,512,512] i32, values 0..4
    int n = in_sizes[0];                        // 33,554,432 (divisible by 4)
    int nvec = n >> 2;

    dice_main_kernel<<<GRID_BLOCKS, 256>>>((const ulonglong2*)pred,
                                           (const int4*)mask,
                                           nvec, n, (float*)d_out);
}

// round 4
// speedup vs baseline: 1.1574x; 1.1574x over previous
#include <cuda_runtime.h>

// MultiClassDiceScore: 3x 5-bin histograms over 33.5M voxels, SIMD nibble/PRMT
// formulation, fused finalize (last-block-done). Memory-bound: 268 MB once.
//
// g_hist layout: [0..3]=pred cnt c0..3, [4..7]=mask cnt c0..3,
//                [8..11]=agree cnt c0..3, [12]=total agreements.
// Class-4 bins derived in the fused finalize. The last block re-zeroes
// g_hist/g_done so every graph replay starts from a clean state.

#define DICE_EPS 1e-7f
#define GRID_BLOCKS 888   // 148 SMs x 6 CTAs: one full wave

__device__ unsigned int g_hist[16];   // zero-initialized at module load
__device__ unsigned int g_done;       // block-completion counter

__device__ __forceinline__ unsigned int prmt(unsigned int a, unsigned int b, unsigned int s) {
    unsigned int d;
    asm("prmt.b32 %0, %1, %2, %3;" : "=r"(d) : "r"(a), "r"(b), "r"(s));
    return d;
}

__device__ __forceinline__ unsigned long long addf32x2(unsigned long long a, unsigned long long b) {
    unsigned long long d;
    asm("add.rn.f32x2 %0, %1, %2;" : "=l"(d) : "l"(a), "l"(b));
    return d;
}

// Pack constants: lo half adds 2^23 (label -> bits[0:4)), hi half adds 2^19
// (label -> bits[4:8)), etc. All sums exact in fp32 for labels 0..4.
#define C01 0x490000004B000000ull   // {2^23, 2^19}
#define C23 0x4500000047000000ull   // {2^15, 2^11}

__global__ __launch_bounds__(256, 6)
void dice_main_kernel(const ulonglong2* __restrict__ pred2,
                      const int4* __restrict__ mask4,
                      int nvec, int n_total,
                      float* __restrict__ out) {
    // Byte-lane accumulators: byte k of aX counts elements at lane k of each
    // 4-element group. Max per-thread groups ~37 << 255: no overflow.
    unsigned int aP0 = 0, aP1 = 0, aP2 = 0, aP3 = 0;
    unsigned int aM0 = 0, aM1 = 0, aM2 = 0, aM3 = 0;
    unsigned int aN0 = 0, aN1 = 0, aN2 = 0, aN3 = 0;
    unsigned int aZ  = 0;

    const int stride = gridDim.x * blockDim.x;
    int i = blockIdx.x * blockDim.x + threadIdx.x;

#pragma unroll 2
    for (; i < nvec; i += stride) {
        ulonglong2 p = __ldcs(&pred2[i]);   // 4 float labels
        int4       m = __ldcs(&mask4[i]);   // 4 int labels

        // selP nibbles = [p0,p1,p2,p3] via packed-f32 exponent trick.
        unsigned long long a01 = addf32x2(p.x, C01);
        unsigned long long a23 = addf32x2(p.y, C23);
        unsigned int selP = (unsigned int)a01 | (unsigned int)(a01 >> 32)
                          | (unsigned int)a23 | (unsigned int)(a23 >> 32);
        // selM nibbles = [m0,m1,m2,m3]
        unsigned int selM = (unsigned int)m.x + ((unsigned int)m.y << 4)
                          + ((unsigned int)m.z << 8) + ((unsigned int)m.w << 12);

        // zd byte k = 1 iff p_k == m_k  (nibble-zero detect, one PRMT LUT)
        unsigned int agr = selP ^ selM;           // nibbles in [0,7]
        unsigned int zd  = prmt(0x00000001u, 0u, agr);
        aZ += zd;

        // per-class equality bytes via PRMT LUTs (classes 0..3; 4 derived)
        unsigned int eP0 = prmt(0x00000001u, 0u, selP);
        unsigned int eP1 = prmt(0x00000100u, 0u, selP);
        unsigned int eP2 = prmt(0x00010000u, 0u, selP);
        unsigned int eP3 = prmt(0x01000000u, 0u, selP);
        aP0 += eP0; aP1 += eP1; aP2 += eP2; aP3 += eP3;

        unsigned int eM0 = prmt(0x00000001u, 0u, selM);
        unsigned int eM1 = prmt(0x00000100u, 0u, selM);
        unsigned int eM2 = prmt(0x00010000u, 0u, selM);
        unsigned int eM3 = prmt(0x01000000u, 0u, selM);
        aM0 += eM0; aM1 += eM1; aM2 += eM2; aM3 += eM3;

        aN0 += eP0 & zd; aN1 += eP1 & zd; aN2 += eP2 & zd; aN3 += eP3 & zd;
    }

    // Horizontal byte sums, warp reduce, block reduce, 13 global atomics/block.
    unsigned int v[13];
    v[0]  = (unsigned int)__dp4a((int)aP0, 0x01010101, 0);
    v[1]  = (unsigned int)__dp4a((int)aP1, 0x01010101, 0);
    v[2]  = (unsigned int)__dp4a((int)aP2, 0x01010101, 0);
    v[3]  = (unsigned int)__dp4a((int)aP3, 0x01010101, 0);
    v[4]  = (unsigned int)__dp4a((int)aM0, 0x01010101, 0);
    v[5]  = (unsigned int)__dp4a((int)aM1, 0x01010101, 0);
    v[6]  = (unsigned int)__dp4a((int)aM2, 0x01010101, 0);
    v[7]  = (unsigned int)__dp4a((int)aM3, 0x01010101, 0);
    v[8]  = (unsigned int)__dp4a((int)aN0, 0x01010101, 0);
    v[9]  = (unsigned int)__dp4a((int)aN1, 0x01010101, 0);
    v[10] = (unsigned int)__dp4a((int)aN2, 0x01010101, 0);
    v[11] = (unsigned int)__dp4a((int)aN3, 0x01010101, 0);
    v[12] = (unsigned int)__dp4a((int)aZ,  0x01010101, 0);

    __shared__ unsigned int sh[13];
    __shared__ bool is_last;
    if (threadIdx.x < 13) sh[threadIdx.x] = 0u;
    __syncthreads();

#pragma unroll
    for (int k = 0; k < 13; k++) {
        unsigned int w = __reduce_add_sync(0xFFFFFFFFu, v[k]);
        if ((threadIdx.x & 31) == 0) atomicAdd(&sh[k], w);
    }
    __syncthreads();
    if (threadIdx.x < 13) atomicAdd(&g_hist[threadIdx.x], sh[threadIdx.x]);

    // Last-block-done: the final arriving block computes dice + resets state.
    if (threadIdx.x == 0) {
        __threadfence();
        unsigned int old = atomicAdd(&g_done, 1u);
        is_last = (old == (unsigned int)(gridDim.x - 1));
    }
    __syncthreads();

    if (is_last && threadIdx.x == 0) {
        unsigned int P[5], M[5], Nm[5];
        unsigned int sp = 0, sm = 0, sn = 0;
#pragma unroll
        for (int c = 0; c < 4; c++) {
            P[c]  = g_hist[c];       sp += P[c];
            M[c]  = g_hist[4 + c];   sm += M[c];
            Nm[c] = g_hist[8 + c];   sn += Nm[c];
        }
        unsigned int Z = g_hist[12];
        P[4]  = (unsigned int)n_total - sp;
        M[4]  = (unsigned int)n_total - sm;
        Nm[4] = Z - sn;

        float s = 0.0f;
#pragma unroll
        for (int c = 0; c < 5; c++) {
            float den1 = (float)P[c];
            float den2 = (float)M[c];
            float num  = (float)Nm[c];
            s += 2.0f * ((num + DICE_EPS) / (den1 + den2 + DICE_EPS));
        }
        out[0] = s * 0.2f;

        // reset state for the next (graph-replayed) launch
#pragma unroll
        for (int k = 0; k < 16; k++) g_hist[k] = 0u;
        __threadfence();
        g_done = 0u;
    }
}

extern "C" void kernel_launch(void* const* d_in, const int* in_sizes, int n_in,
                              void* d_out, int out_size) {
    const float* pred = (const float*)d_in[0];  // [128,1,512,512] f32, values 0..4
    const int*   mask = (const int*)d_in[1];    // [1,128,512,512] i32, values 0..4
    int n = in_sizes[0];                        // 33,554,432 (divisible by 4)
    int nvec = n >> 2;

    dice_main_kernel<<<GRID_BLOCKS, 256>>>((const ulonglong2*)pred,
                                           (const int4*)mask,
                                           nvec, n, (float*)d_out);
}

// round 5
// speedup vs baseline: 1.1922x; 1.0300x over previous
#include <cuda_runtime.h>

// MultiClassDiceScore: histograms over 33.5M voxels, SIMD nibble/PRMT,
// fused finalize. Memory-bound: 268 MB streamed once (~41us LTS-cap floor).
//
// Register-slimmed for occupancy 8: dice only needs den1+den2, so pred/mask
// histograms are fused into one sum-accumulator per class (value<=2/iter).
// g_hist: [0..3]=den1+den2 for c0..3, [4..7]=num c0..3, [8]=total agreements.
// Class-4 bins derived in finalize; last block resets state for graph replay.

#define DICE_EPS 1e-7f
#define GRID_BLOCKS 1184   // 148 SMs x 8 CTAs: one full wave

__device__ unsigned int g_hist[12];   // zero-initialized at module load
__device__ unsigned int g_done;       // block-completion counter

__device__ __forceinline__ unsigned int prmt(unsigned int a, unsigned int b, unsigned int s) {
    unsigned int d;
    asm("prmt.b32 %0, %1, %2, %3;" : "=r"(d) : "r"(a), "r"(b), "r"(s));
    return d;
}

__device__ __forceinline__ unsigned long long addf32x2(unsigned long long a, unsigned long long b) {
    unsigned long long d;
    asm("add.rn.f32x2 %0, %1, %2;" : "=l"(d) : "l"(a), "l"(b));
    return d;
}

// Pack constants: lo half adds 2^23 (label -> bits[0:4)), hi half adds 2^19
// (label -> bits[4:8)), etc. All sums exact in fp32 for labels 0..4.
#define C01 0x490000004B000000ull   // {2^23, 2^19}
#define C23 0x4500000047000000ull   // {2^15, 2^11}

__global__ __launch_bounds__(256, 8)
void dice_main_kernel(const ulonglong2* __restrict__ pred2,
                      const int4* __restrict__ mask4,
                      int nvec, int n_total,
                      float* __restrict__ out) {
    // Byte-lane accumulators. Max per-thread groups ~28; aS bytes <= 56,
    // aN/aZ bytes <= 28 — far below 255, no overflow.
    unsigned int aS0 = 0, aS1 = 0, aS2 = 0, aS3 = 0;   // (p==c) + (m==c)
    unsigned int aN0 = 0, aN1 = 0, aN2 = 0, aN3 = 0;   // p==m==c
    unsigned int aZ  = 0;                              // p==m (any class)

    const int stride = gridDim.x * blockDim.x;
    int i = blockIdx.x * blockDim.x + threadIdx.x;

#pragma unroll 2
    for (; i < nvec; i += stride) {
        ulonglong2 p = __ldcs(&pred2[i]);   // 4 float labels
        int4       m = __ldcs(&mask4[i]);   // 4 int labels

        // selP nibbles = [p0,p1,p2,p3] via packed-f32 exponent trick.
        unsigned long long a01 = addf32x2(p.x, C01);
        unsigned long long a23 = addf32x2(p.y, C23);
        unsigned int selP = (unsigned int)a01 | (unsigned int)(a01 >> 32)
                          | (unsigned int)a23 | (unsigned int)(a23 >> 32);
        // selM nibbles = [m0,m1,m2,m3]
        unsigned int selM = (unsigned int)m.x + ((unsigned int)m.y << 4)
                          + ((unsigned int)m.z << 8) + ((unsigned int)m.w << 12);

        // zd byte k = 1 iff p_k == m_k  (nibble-zero detect, one PRMT LUT)
        unsigned int zd = prmt(0x00000001u, 0u, selP ^ selM);
        aZ += zd;

        // per-class equality bytes via PRMT LUTs (classes 0..3; 4 derived)
        unsigned int eP0 = prmt(0x00000001u, 0u, selP);
        unsigned int eP1 = prmt(0x00000100u, 0u, selP);
        unsigned int eP2 = prmt(0x00010000u, 0u, selP);
        unsigned int eP3 = prmt(0x01000000u, 0u, selP);

        aS0 += eP0 + prmt(0x00000001u, 0u, selM);
        aS1 += eP1 + prmt(0x00000100u, 0u, selM);
        aS2 += eP2 + prmt(0x00010000u, 0u, selM);
        aS3 += eP3 + prmt(0x01000000u, 0u, selM);

        aN0 += eP0 & zd; aN1 += eP1 & zd; aN2 += eP2 & zd; aN3 += eP3 & zd;
    }

    // Horizontal byte sums, warp reduce, block reduce, 9 global atomics/block.
    unsigned int v[9];
    v[0] = (unsigned int)__dp4a((int)aS0, 0x01010101, 0);
    v[1] = (unsigned int)__dp4a((int)aS1, 0x01010101, 0);
    v[2] = (unsigned int)__dp4a((int)aS2, 0x01010101, 0);
    v[3] = (unsigned int)__dp4a((int)aS3, 0x01010101, 0);
    v[4] = (unsigned int)__dp4a((int)aN0, 0x01010101, 0);
    v[5] = (unsigned int)__dp4a((int)aN1, 0x01010101, 0);
    v[6] = (unsigned int)__dp4a((int)aN2, 0x01010101, 0);
    v[7] = (unsigned int)__dp4a((int)aN3, 0x01010101, 0);
    v[8] = (unsigned int)__dp4a((int)aZ,  0x01010101, 0);

    __shared__ unsigned int sh[9];
    __shared__ bool is_last;
    if (threadIdx.x < 9) sh[threadIdx.x] = 0u;
    __syncthreads();

#pragma unroll
    for (int k = 0; k < 9; k++) {
        unsigned int w = __reduce_add_sync(0xFFFFFFFFu, v[k]);
        if ((threadIdx.x & 31) == 0) atomicAdd(&sh[k], w);
    }
    __syncthreads();
    if (threadIdx.x < 9) atomicAdd(&g_hist[threadIdx.x], sh[threadIdx.x]);

    // Last-block-done: the final arriving block computes dice + resets state.
    if (threadIdx.x == 0) {
        __threadfence();
        unsigned int old = atomicAdd(&g_done, 1u);
        is_last = (old == (unsigned int)(gridDim.x - 1));
    }
    __syncthreads();

    if (is_last && threadIdx.x == 0) {
        unsigned int S[5], Nm[5];
        unsigned int ss = 0, sn = 0;
#pragma unroll
        for (int c = 0; c < 4; c++) {
            S[c]  = g_hist[c];       ss += S[c];
            Nm[c] = g_hist[4 + c];   sn += Nm[c];
        }
        unsigned int Z = g_hist[8];
        S[4]  = 2u * (unsigned int)n_total - ss;   // den1[4]+den2[4]
        Nm[4] = Z - sn;

        float s = 0.0f;
#pragma unroll
        for (int c = 0; c < 5; c++) {
            s += 2.0f * (((float)Nm[c] + DICE_EPS) / ((float)S[c] + DICE_EPS));
        }
        out[0] = s * 0.2f;

        // reset state for the next (graph-replayed) launch
#pragma unroll
        for (int k = 0; k < 12; k++) g_hist[k] = 0u;
        __threadfence();
        g_done = 0u;
    }
}

extern "C" void kernel_launch(void* const* d_in, const int* in_sizes, int n_in,
                              void* d_out, int out_size) {
    const float* pred = (const float*)d_in[0];  // [128,1,512,512] f32, values 0..4
    const int*   mask = (const int*)d_in[1];    // [1,128,512,512] i32, values 0..4
    int n = in_sizes[0];                        // 33,554,432 (divisible by 4)
    int nvec = n >> 2;

    dice_main_kernel<<<GRID_BLOCKS, 256>>>((const ulonglong2*)pred,
                                           (const int4*)mask,
                                           nvec, n, (float*)d_out);
}